// round 2
// baseline (speedup 1.0000x reference)
#include <cuda_runtime.h>
#include <cstdint>
#include <math.h>

// Problem constants (fixed by the dataset)
#define NF 64     // N_FIXED
#define Bn 5000   // batters
#define Ln 10     // leagues
#define Tn 25     // seasons
#define Kn 8      // outputs

// Scratch: u-table [t][b][l][k]  (40 MB)
__device__ float g_u[(size_t)Tn * Bn * Ln * Kn];

// ---------------------------------------------------------------------------
// Kernel 1: fused cholesky-diag + AR(1) scan.
// Each block: copy Sigma (8 x 10x10) to smem, 8 threads factor it in-place,
// extract diag d[l][k]. Then one thread per (b,l,k) chain, serial over T=25:
//   u[0] = eps[b,l,0,k];  u[t] = rho*u[t-1] + d*eps[b,l,t,k]
// eps layout: [B][L][T][K]. u written as [t][b][l][k] so gather rows are 32B.
// ---------------------------------------------------------------------------
__global__ void __launch_bounds__(256)
scan_kernel(const float* __restrict__ eps,
            const float* __restrict__ raw_rho,
            const float* __restrict__ Sigma) {
    __shared__ float sA[Kn][Ln * Ln];   // 3.2 KB
    __shared__ float sd[Ln][Kn];

    int tid = threadIdx.x;
    for (int i = tid; i < Kn * Ln * Ln; i += 256)
        ((float*)sA)[i] = Sigma[i];    // Sigma[k][i][j] contiguous
    __syncthreads();

    if (tid < Kn) {
        float* A = sA[tid];
        for (int i = 0; i < Ln; i++) {
            for (int j = 0; j < i; j++) {
                float s = A[i * Ln + j];
                for (int p = 0; p < j; p++) s -= A[i * Ln + p] * A[j * Ln + p];
                A[i * Ln + j] = __fdividef(s, A[j * Ln + j]);
            }
            float s = A[i * Ln + i];
            for (int p = 0; p < i; p++) s -= A[i * Ln + p] * A[i * Ln + p];
            float dii = sqrtf(s);
            A[i * Ln + i] = dii;
            sd[i][tid] = dii;
        }
    }
    __syncthreads();

    int idx = blockIdx.x * blockDim.x + tid;
    if (idx >= Bn * Ln * Kn) return;
    int k = idx & (Kn - 1);
    int l = (idx / Kn) % Ln;
    int b = idx / (Kn * Ln);

    float rho = tanhf(raw_rho[l * Kn + k]);
    float d   = sd[l][k];

    const float* e = eps + ((size_t)(b * Ln + l) * Tn) * Kn + k;
    float* up = g_u + (size_t)(b * Ln + l) * Kn + k;   // t=0 slot
    const size_t ustep = (size_t)Bn * Ln * Kn;

    float u = e[0];
    up[0] = u;
#pragma unroll
    for (int t = 1; t < Tn; t++) {
        u = fmaf(rho, u, d * e[(size_t)t * Kn]);
        up[(size_t)t * ustep] = u;
    }
}

// ---------------------------------------------------------------------------
// Kernel 2: out[n,:] = X[n,:] @ beta + u[s,b,l,:]
// Warp = 4 rows x 8 lanes. Lane t of a row loads xp[t] and xp[8+t], so every
// LDG.128 covers whole 128B lines (nL=4 per LDG, no wavefront amplification).
// Partial dot products (4 x f32x2 accumulators) butterfly-reduced over the
// 8-lane group; lanes t=0,1 gather u and store one float4 each.
// ---------------------------------------------------------------------------
#define FMA2(d_, a_, b_, c_) \
    asm("fma.rn.f32x2 %0, %1, %2, %3;" : "=l"(d_) : "l"(a_), "l"(b_), "l"(c_))
#define ADD2(d_, a_, b_) \
    asm("add.rn.f32x2 %0, %1, %2;" : "=l"(d_) : "l"(a_), "l"(b_))

__global__ void __launch_bounds__(256)
main_kernel(const float* __restrict__ X,
            const int* __restrict__ batter_ids,
            const int* __restrict__ league_ids,
            const int* __restrict__ season_ids,
            const float* __restrict__ beta,
            float* __restrict__ out, int N) {
    __shared__ unsigned long long sbeta[NF * Kn / 2];   // 256 pairs, 2 KB
    for (int i = threadIdx.x; i < NF * Kn / 2; i += blockDim.x)
        sbeta[i] = ((const unsigned long long*)beta)[i];
    __syncthreads();

    int lane = threadIdx.x & 31;
    int wrp  = threadIdx.x >> 5;
    int r    = lane >> 3;        // row within warp group (0..3)
    int t    = lane & 7;         // lane within row (0..7)
    int n    = blockIdx.x * 32 + wrp * 4 + r;
    if (n >= N) return;

    const float4* xp = (const float4*)(X + (size_t)n * NF);
    float4 xa = xp[t];       // covers line 0 of the row across t=0..7
    float4 xb = xp[8 + t];   // covers line 1

    unsigned long long acc0 = 0ull, acc1 = 0ull, acc2 = 0ull, acc3 = 0ull;

    float xs[8] = {xa.x, xa.y, xa.z, xa.w, xb.x, xb.y, xb.z, xb.w};
#pragma unroll
    for (int i = 0; i < 8; i++) {
        int f = (i < 4) ? (t * 4 + i) : (32 + t * 4 + (i - 4));
        unsigned int xw = __float_as_uint(xs[i]);
        unsigned long long xq;
        asm("mov.b64 %0, {%1,%2};" : "=l"(xq) : "r"(xw), "r"(xw));
        FMA2(acc0, xq, sbeta[f * 4 + 0], acc0);
        FMA2(acc1, xq, sbeta[f * 4 + 1], acc1);
        FMA2(acc2, xq, sbeta[f * 4 + 2], acc2);
        FMA2(acc3, xq, sbeta[f * 4 + 3], acc3);
    }

    // Butterfly reduce over the 8-lane group (xor 1,2,4)
#pragma unroll
    for (int ofs = 1; ofs < 8; ofs <<= 1) {
        unsigned long long p0 = __shfl_xor_sync(0xffffffffu, acc0, ofs);
        unsigned long long p1 = __shfl_xor_sync(0xffffffffu, acc1, ofs);
        unsigned long long p2 = __shfl_xor_sync(0xffffffffu, acc2, ofs);
        unsigned long long p3 = __shfl_xor_sync(0xffffffffu, acc3, ofs);
        ADD2(acc0, acc0, p0);
        ADD2(acc1, acc1, p1);
        ADD2(acc2, acc2, p2);
        ADD2(acc3, acc3, p3);
    }

    if (t < 2) {
        int s = season_ids[n];
        int b = batter_ids[n];
        int l = league_ids[n];
        const float4 u = *(const float4*)(
            g_u + ((size_t)(s * Bn + b) * Ln + l) * Kn + t * 4);

        unsigned long long pA = (t == 0) ? acc0 : acc2;
        unsigned long long pB = (t == 0) ? acc1 : acc3;
        float f0, f1, f2, f3;
        asm("mov.b64 {%0,%1}, %2;" : "=f"(f0), "=f"(f1) : "l"(pA));
        asm("mov.b64 {%0,%1}, %2;" : "=f"(f2), "=f"(f3) : "l"(pB));

        float4 o = make_float4(f0 + u.x, f1 + u.y, f2 + u.z, f3 + u.w);
        ((float4*)(out + (size_t)n * Kn))[t] = o;
    }
}

// ---------------------------------------------------------------------------
// Launch: inputs in metadata order:
//   0:X  1:batter_ids  2:league_ids  3:season_ids  4:beta  5:raw_rho
//   6:Sigma  7:eps
// ---------------------------------------------------------------------------
extern "C" void kernel_launch(void* const* d_in, const int* in_sizes, int n_in,
                              void* d_out, int out_size) {
    const float* X        = (const float*)d_in[0];
    const int*   bid      = (const int*)d_in[1];
    const int*   lid      = (const int*)d_in[2];
    const int*   sid      = (const int*)d_in[3];
    const float* beta     = (const float*)d_in[4];
    const float* raw_rho  = (const float*)d_in[5];
    const float* Sigma    = (const float*)d_in[6];
    const float* eps      = (const float*)d_in[7];
    float*       out      = (float*)d_out;

    const int N = in_sizes[1];  // rows

    int chains = Bn * Ln * Kn;
    scan_kernel<<<(chains + 255) / 256, 256>>>(eps, raw_rho, Sigma);

    main_kernel<<<(N + 31) / 32, 256>>>(X, bid, lid, sid, beta, out, N);
}

// round 3
// speedup vs baseline: 1.8749x; 1.8749x over previous
#include <cuda_runtime.h>
#include <cstdint>
#include <math.h>

#define NF 64
#define Bn 5000
#define Ln 10
#define Tn 25
#define Kn 8

// Scratch: u-table [t][b][l][k] (40 MB) so gather rows are contiguous 32B.
__device__ float g_u[(size_t)Tn * Bn * Ln * Kn];

// ---------------------------------------------------------------------------
// Kernel 1: fused cholesky-diag + AR(1) scan, float4-vectorized.
// Thread = (b, l, k-quad). Fully coalesced loads/stores.
// ---------------------------------------------------------------------------
__global__ void __launch_bounds__(256)
scan_kernel(const float* __restrict__ eps,
            const float* __restrict__ raw_rho,
            const float* __restrict__ Sigma) {
    __shared__ float sA[Kn][Ln * Ln];
    __shared__ float sd[Ln][Kn];

    int tid = threadIdx.x;
    for (int i = tid; i < Kn * Ln * Ln; i += 256)
        ((float*)sA)[i] = Sigma[i];
    __syncthreads();

    if (tid < Kn) {
        float* A = sA[tid];
        for (int i = 0; i < Ln; i++) {
            for (int j = 0; j < i; j++) {
                float s = A[i * Ln + j];
                for (int p = 0; p < j; p++) s -= A[i * Ln + p] * A[j * Ln + p];
                A[i * Ln + j] = __fdividef(s, A[j * Ln + j]);
            }
            float s = A[i * Ln + i];
            for (int p = 0; p < i; p++) s -= A[i * Ln + p] * A[i * Ln + p];
            float dii = sqrtf(s);
            A[i * Ln + i] = dii;
            sd[i][tid] = dii;
        }
    }
    __syncthreads();

    int idx = blockIdx.x * blockDim.x + tid;        // (b, l, kq)
    if (idx >= Bn * Ln * 2) return;
    int kq = idx & 1;
    int l  = (idx >> 1) % Ln;
    int b  = idx / (2 * Ln);

    float4 rr = *(const float4*)(raw_rho + l * Kn + kq * 4);
    float4 rho = make_float4(tanhf(rr.x), tanhf(rr.y), tanhf(rr.z), tanhf(rr.w));
    float4 d = *(float4*)&sd[l][kq * 4];

    const float4* e = (const float4*)(eps + ((size_t)(b * Ln + l) * Tn) * Kn + kq * 4);
    float4* up = (float4*)(g_u + (size_t)(b * Ln + l) * Kn + kq * 4);
    const size_t ustep = (size_t)Bn * Ln * Kn / 4;   // in float4 units

    float4 u = e[0];                                  // e step = Kn/4 = 2 float4
    up[0] = u;
#pragma unroll
    for (int t = 1; t < Tn; t++) {
        float4 ev = e[t * 2];
        u.x = fmaf(rho.x, u.x, d.x * ev.x);
        u.y = fmaf(rho.y, u.y, d.y * ev.y);
        u.z = fmaf(rho.z, u.z, d.z * ev.z);
        u.w = fmaf(rho.w, u.w, d.w * ev.w);
        up[(size_t)t * ustep] = u;
    }
}

// ---------------------------------------------------------------------------
// Kernel 2: out[n,:] = X[n,:] @ beta + u[s,b,l,:]
// Warp = 8 rows x (4 lanes... actually rows r=0..3 twice) : lane = r*8+t.
// Lane t loads x-chunks [4t..4t+3] and [32+4t..35+4t] -> every LDG.128 covers
// whole 128B lines. beta held in 32 packed-f32x2 REGISTERS per lane (no LDS).
// Halving butterfly (4 shfl.64 per row-set) leaves K-pair p=t>>1 on even lanes.
// ---------------------------------------------------------------------------
#define FMA2(d_, a_, b_, c_) \
    asm("fma.rn.f32x2 %0, %1, %2, %3;" : "=l"(d_) : "l"(a_), "l"(b_), "l"(c_))
#define ADD2(d_, a_, b_) \
    asm("add.rn.f32x2 %0, %1, %2;" : "=l"(d_) : "l"(a_), "l"(b_))

__device__ __forceinline__ unsigned long long dupf(float x) {
    unsigned int w = __float_as_uint(x);
    unsigned long long q;
    asm("mov.b64 %0, {%1,%2};" : "=l"(q) : "r"(w), "r"(w));
    return q;
}

__global__ void __launch_bounds__(256)
main_kernel(const float* __restrict__ X,
            const int* __restrict__ batter_ids,
            const int* __restrict__ league_ids,
            const int* __restrict__ season_ids,
            const float* __restrict__ beta,
            float* __restrict__ out, int N) {
    int lane = threadIdx.x & 31;
    int wrp  = threadIdx.x >> 5;
    int r    = lane >> 3;            // 0..3
    int t    = lane & 7;             // 0..7

    int n1 = blockIdx.x * 64 + wrp * 8 + r;   // first row
    int n2 = n1 + 4;                          // second row
    int c1 = min(n1, N - 1), c2 = min(n2, N - 1);

    // beta rows for this lane: f = 4t+i (i<4), 32+4t+i-4 (i>=4); 4 pairs each.
    unsigned long long B[8][4];
    const ulonglong2* bp = (const ulonglong2*)beta;
#pragma unroll
    for (int i = 0; i < 8; i++) {
        int f = (i < 4) ? (4 * t + i) : (32 + 4 * t + i - 4);
        ulonglong2 lo = bp[f * 2];
        ulonglong2 hi = bp[f * 2 + 1];
        B[i][0] = lo.x; B[i][1] = lo.y; B[i][2] = hi.x; B[i][3] = hi.y;
    }

    const float4* xp1 = (const float4*)(X + (size_t)c1 * NF);
    const float4* xp2 = (const float4*)(X + (size_t)c2 * NF);
    float4 xa1 = xp1[t], xb1 = xp1[8 + t];
    float4 xa2 = xp2[t], xb2 = xp2[8 + t];

    unsigned long long acc1[4] = {0, 0, 0, 0};
    unsigned long long acc2[4] = {0, 0, 0, 0};
    float xs1[8] = {xa1.x, xa1.y, xa1.z, xa1.w, xb1.x, xb1.y, xb1.z, xb1.w};
    float xs2[8] = {xa2.x, xa2.y, xa2.z, xa2.w, xb2.x, xb2.y, xb2.z, xb2.w};

#pragma unroll
    for (int i = 0; i < 8; i++) {
        unsigned long long q1 = dupf(xs1[i]);
        unsigned long long q2 = dupf(xs2[i]);
#pragma unroll
        for (int j = 0; j < 4; j++) {
            FMA2(acc1[j], q1, B[i][j], acc1[j]);
            FMA2(acc2[j], q2, B[i][j], acc2[j]);
        }
    }

    // Halving butterfly over the 8-lane group; result: lane holds pair p=t>>1.
    unsigned long long C1, C2;
#pragma unroll
    for (int v = 0; v < 2; v++) {
        unsigned long long* a = v ? acc2 : acc1;
        bool hi4 = (t & 4) != 0;
        unsigned long long s0 = hi4 ? a[0] : a[2];
        unsigned long long s1 = hi4 ? a[1] : a[3];
        unsigned long long k0 = hi4 ? a[2] : a[0];
        unsigned long long k1 = hi4 ? a[3] : a[1];
        unsigned long long r0 = __shfl_xor_sync(0xffffffffu, s0, 4);
        unsigned long long r1 = __shfl_xor_sync(0xffffffffu, s1, 4);
        ADD2(k0, k0, r0);
        ADD2(k1, k1, r1);

        bool hi2 = (t & 2) != 0;
        unsigned long long s = hi2 ? k0 : k1;
        unsigned long long k = hi2 ? k1 : k0;
        unsigned long long rv = __shfl_xor_sync(0xffffffffu, s, 2);
        ADD2(k, k, rv);

        unsigned long long rw = __shfl_xor_sync(0xffffffffu, k, 1);
        ADD2(k, k, rw);
        if (v) C2 = k; else C1 = k;
    }

    // Even lanes: gather u pair and store 8B per row-set.
    if ((t & 1) == 0) {
        int p = t >> 1;
#pragma unroll
        for (int v = 0; v < 2; v++) {
            int n = v ? n2 : n1;
            if (n < N) {
                int s = season_ids[n];
                int b = batter_ids[n];
                int l = league_ids[n];
                const float2 u = *(const float2*)(
                    g_u + ((size_t)(s * Bn + b) * Ln + l) * Kn + p * 2);
                unsigned long long C = v ? C2 : C1;
                float f0, f1;
                asm("mov.b64 {%0,%1}, %2;" : "=f"(f0), "=f"(f1) : "l"(C));
                float2 o = make_float2(f0 + u.x, f1 + u.y);
                *(float2*)(out + (size_t)n * Kn + p * 2) = o;
            }
        }
    }
}

// ---------------------------------------------------------------------------
extern "C" void kernel_launch(void* const* d_in, const int* in_sizes, int n_in,
                              void* d_out, int out_size) {
    const float* X       = (const float*)d_in[0];
    const int*   bid     = (const int*)d_in[1];
    const int*   lid     = (const int*)d_in[2];
    const int*   sid     = (const int*)d_in[3];
    const float* beta    = (const float*)d_in[4];
    const float* raw_rho = (const float*)d_in[5];
    const float* Sigma   = (const float*)d_in[6];
    const float* eps     = (const float*)d_in[7];
    float*       out     = (float*)d_out;

    const int N = in_sizes[1];

    int chains4 = Bn * Ln * 2;   // (b,l,k-quad) threads
    scan_kernel<<<(chains4 + 255) / 256, 256>>>(eps, raw_rho, Sigma);

    main_kernel<<<(N + 63) / 64, 256>>>(X, bid, lid, sid, beta, out, N);
}

// round 4
// speedup vs baseline: 3.7017x; 1.9744x over previous
#include <cuda_runtime.h>
#include <cstdint>
#include <math.h>

#define NF 64
#define Bn 5000
#define Ln 10
#define Tn 25
#define Kn 8

// Scratch: u-table [t][b][l][k] (40 MB) so gather rows are contiguous 32B.
__device__ float g_u[(size_t)Tn * Bn * Ln * Kn];

// ---------------------------------------------------------------------------
// Kernel 1: fused cholesky-diag + AR(1) scan, float4-vectorized.
// Thread = (b, l, k-quad). Fully coalesced loads/stores.
// ---------------------------------------------------------------------------
__global__ void __launch_bounds__(256)
scan_kernel(const float* __restrict__ eps,
            const float* __restrict__ raw_rho,
            const float* __restrict__ Sigma) {
    __shared__ float sA[Kn][Ln * Ln];
    __shared__ float sd[Ln][Kn];

    int tid = threadIdx.x;
    for (int i = tid; i < Kn * Ln * Ln; i += 256)
        ((float*)sA)[i] = Sigma[i];
    __syncthreads();

    if (tid < Kn) {
        float* A = sA[tid];
        for (int i = 0; i < Ln; i++) {
            for (int j = 0; j < i; j++) {
                float s = A[i * Ln + j];
                for (int p = 0; p < j; p++) s -= A[i * Ln + p] * A[j * Ln + p];
                A[i * Ln + j] = __fdividef(s, A[j * Ln + j]);
            }
            float s = A[i * Ln + i];
            for (int p = 0; p < i; p++) s -= A[i * Ln + p] * A[i * Ln + p];
            float dii = sqrtf(s);
            A[i * Ln + i] = dii;
            sd[i][tid] = dii;
        }
    }
    __syncthreads();

    int idx = blockIdx.x * blockDim.x + tid;        // (b, l, kq)
    if (idx >= Bn * Ln * 2) return;
    int kq = idx & 1;
    int l  = (idx >> 1) % Ln;
    int b  = idx / (2 * Ln);

    float4 rr = *(const float4*)(raw_rho + l * Kn + kq * 4);
    float4 rho = make_float4(tanhf(rr.x), tanhf(rr.y), tanhf(rr.z), tanhf(rr.w));
    float4 d = *(float4*)&sd[l][kq * 4];

    const float4* e = (const float4*)(eps + ((size_t)(b * Ln + l) * Tn) * Kn + kq * 4);
    float4* up = (float4*)(g_u + (size_t)(b * Ln + l) * Kn + kq * 4);
    const size_t ustep = (size_t)Bn * Ln * Kn / 4;   // in float4 units

    float4 u = __ldcs(&e[0]);
    up[0] = u;
#pragma unroll
    for (int t = 1; t < Tn; t++) {
        float4 ev = __ldcs(&e[t * 2]);
        u.x = fmaf(rho.x, u.x, d.x * ev.x);
        u.y = fmaf(rho.y, u.y, d.y * ev.y);
        u.z = fmaf(rho.z, u.z, d.z * ev.z);
        u.w = fmaf(rho.w, u.w, d.w * ev.w);
        up[(size_t)t * ustep] = u;
    }
}

// ---------------------------------------------------------------------------
// Kernel 2 (persistent grid-stride):
//   out[n,:] = X[n,:] @ beta + u[s,b,l,:]
// Warp layout: lane = r*8+t (r=0..3 rows, t=0..7 feature-chunks).
// Lane t loads X float4 chunks t and 8+t -> every LDG.128 covers whole 128B
// lines. beta held in 64 REGISTERS per lane, loaded ONCE per warp and
// amortized over ~50 row-groups via grid-stride. No shared memory.
// ---------------------------------------------------------------------------
#define FMA2(d_, a_, b_, c_) \
    asm("fma.rn.f32x2 %0, %1, %2, %3;" : "=l"(d_) : "l"(a_), "l"(b_), "l"(c_))
#define ADD2(d_, a_, b_) \
    asm("add.rn.f32x2 %0, %1, %2;" : "=l"(d_) : "l"(a_), "l"(b_))

__device__ __forceinline__ unsigned long long dupf(float x) {
    unsigned int w = __float_as_uint(x);
    unsigned long long q;
    asm("mov.b64 %0, {%1,%2};" : "=l"(q) : "r"(w), "r"(w));
    return q;
}

__global__ void __launch_bounds__(256, 2)
main_kernel(const float* __restrict__ X,
            const int* __restrict__ batter_ids,
            const int* __restrict__ league_ids,
            const int* __restrict__ season_ids,
            const float* __restrict__ beta,
            float* __restrict__ out, int N) {
    int lane = threadIdx.x & 31;
    int r    = lane >> 3;            // 0..3
    int t    = lane & 7;             // 0..7

    // beta rows for this lane: f = 4t+i (i<4), 32+4t+(i-4) (i>=4); 4 pairs each.
    unsigned long long B[8][4];
    const ulonglong2* bp = (const ulonglong2*)beta;
#pragma unroll
    for (int i = 0; i < 8; i++) {
        int f = (i < 4) ? (4 * t + i) : (32 + 4 * t + i - 4);
        ulonglong2 lo = __ldg(&bp[f * 2]);
        ulonglong2 hi = __ldg(&bp[f * 2 + 1]);
        B[i][0] = lo.x; B[i][1] = lo.y; B[i][2] = hi.x; B[i][3] = hi.y;
    }

    int warpsPerBlock = blockDim.x >> 5;
    int gwarp = blockIdx.x * warpsPerBlock + (threadIdx.x >> 5);
    int totalWarps = gridDim.x * warpsPerBlock;
    int G = (N + 7) >> 3;            // 8-row groups

    for (int g = gwarp; g < G; g += totalWarps) {
        int n1 = g * 8 + r;
        int n2 = n1 + 4;
        int c1 = min(n1, N - 1), c2 = min(n2, N - 1);

        const float4* xp1 = (const float4*)(X + (size_t)c1 * NF);
        const float4* xp2 = (const float4*)(X + (size_t)c2 * NF);
        float4 xa1 = __ldcs(&xp1[t]), xb1 = __ldcs(&xp1[8 + t]);
        float4 xa2 = __ldcs(&xp2[t]), xb2 = __ldcs(&xp2[8 + t]);

        unsigned long long acc1[4] = {0, 0, 0, 0};
        unsigned long long acc2[4] = {0, 0, 0, 0};
        float xs1[8] = {xa1.x, xa1.y, xa1.z, xa1.w, xb1.x, xb1.y, xb1.z, xb1.w};
        float xs2[8] = {xa2.x, xa2.y, xa2.z, xa2.w, xb2.x, xb2.y, xb2.z, xb2.w};

#pragma unroll
        for (int i = 0; i < 8; i++) {
            unsigned long long q1 = dupf(xs1[i]);
            unsigned long long q2 = dupf(xs2[i]);
#pragma unroll
            for (int j = 0; j < 4; j++) {
                FMA2(acc1[j], q1, B[i][j], acc1[j]);
                FMA2(acc2[j], q2, B[i][j], acc2[j]);
            }
        }

        // Halving butterfly over the 8-lane group; lane ends with pair p=t>>1.
        unsigned long long C1, C2;
#pragma unroll
        for (int v = 0; v < 2; v++) {
            unsigned long long* a = v ? acc2 : acc1;
            bool hi4 = (t & 4) != 0;
            unsigned long long s0 = hi4 ? a[0] : a[2];
            unsigned long long s1 = hi4 ? a[1] : a[3];
            unsigned long long k0 = hi4 ? a[2] : a[0];
            unsigned long long k1 = hi4 ? a[3] : a[1];
            unsigned long long r0 = __shfl_xor_sync(0xffffffffu, s0, 4);
            unsigned long long r1 = __shfl_xor_sync(0xffffffffu, s1, 4);
            ADD2(k0, k0, r0);
            ADD2(k1, k1, r1);

            bool hi2 = (t & 2) != 0;
            unsigned long long s = hi2 ? k0 : k1;
            unsigned long long k = hi2 ? k1 : k0;
            unsigned long long rv = __shfl_xor_sync(0xffffffffu, s, 2);
            ADD2(k, k, rv);

            unsigned long long rw = __shfl_xor_sync(0xffffffffu, k, 1);
            ADD2(k, k, rw);
            if (v) C2 = k; else C1 = k;
        }

        if ((t & 1) == 0) {
            int p = t >> 1;
#pragma unroll
            for (int v = 0; v < 2; v++) {
                int n = v ? n2 : n1;
                if (n < N) {
                    int s = season_ids[n];
                    int b = batter_ids[n];
                    int l = league_ids[n];
                    const float2 u = *(const float2*)(
                        g_u + ((size_t)(s * Bn + b) * Ln + l) * Kn + p * 2);
                    unsigned long long C = v ? C2 : C1;
                    float f0, f1;
                    asm("mov.b64 {%0,%1}, %2;" : "=f"(f0), "=f"(f1) : "l"(C));
                    float2 o = make_float2(f0 + u.x, f1 + u.y);
                    *(float2*)(out + (size_t)n * Kn + p * 2) = o;
                }
            }
        }
    }
}

// ---------------------------------------------------------------------------
extern "C" void kernel_launch(void* const* d_in, const int* in_sizes, int n_in,
                              void* d_out, int out_size) {
    const float* X       = (const float*)d_in[0];
    const int*   bid     = (const int*)d_in[1];
    const int*   lid     = (const int*)d_in[2];
    const int*   sid     = (const int*)d_in[3];
    const float* beta    = (const float*)d_in[4];
    const float* raw_rho = (const float*)d_in[5];
    const float* Sigma   = (const float*)d_in[6];
    const float* eps     = (const float*)d_in[7];
    float*       out     = (float*)d_out;

    const int N = in_sizes[1];

    int chains4 = Bn * Ln * 2;   // (b,l,k-quad) threads
    scan_kernel<<<(chains4 + 255) / 256, 256>>>(eps, raw_rho, Sigma);

    // Persistent grid: ~2 blocks/SM (128-reg cap via launch_bounds).
    main_kernel<<<304, 256>>>(X, bid, lid, sid, beta, out, N);
}

// round 5
// speedup vs baseline: 3.9364x; 1.0634x over previous
#include <cuda_runtime.h>
#include <cstdint>
#include <math.h>

#define NF 64
#define Bn 5000
#define Ln 10
#define Tn 25
#define Kn 8

typedef unsigned long long ull;

// Scratch: u-table [t][b][l][k] (40 MB) so gather rows are contiguous 32B.
__device__ float g_u[(size_t)Tn * Bn * Ln * Kn];

// ---------------------------------------------------------------------------
// Kernel 1: fused cholesky-diag + AR(1) scan, float4-vectorized.
// ---------------------------------------------------------------------------
__global__ void __launch_bounds__(256)
scan_kernel(const float* __restrict__ eps,
            const float* __restrict__ raw_rho,
            const float* __restrict__ Sigma) {
    __shared__ float sA[Kn][Ln * Ln];
    __shared__ float sd[Ln][Kn];

    int tid = threadIdx.x;
    for (int i = tid; i < Kn * Ln * Ln; i += 256)
        ((float*)sA)[i] = Sigma[i];
    __syncthreads();

    if (tid < Kn) {
        float* A = sA[tid];
        for (int i = 0; i < Ln; i++) {
            for (int j = 0; j < i; j++) {
                float s = A[i * Ln + j];
                for (int p = 0; p < j; p++) s -= A[i * Ln + p] * A[j * Ln + p];
                A[i * Ln + j] = __fdividef(s, A[j * Ln + j]);
            }
            float s = A[i * Ln + i];
            for (int p = 0; p < i; p++) s -= A[i * Ln + p] * A[i * Ln + p];
            float dii = sqrtf(s);
            A[i * Ln + i] = dii;
            sd[i][tid] = dii;
        }
    }
    __syncthreads();

    int idx = blockIdx.x * blockDim.x + tid;        // (b, l, kq)
    if (idx >= Bn * Ln * 2) return;
    int kq = idx & 1;
    int l  = (idx >> 1) % Ln;
    int b  = idx / (2 * Ln);

    float4 rr = *(const float4*)(raw_rho + l * Kn + kq * 4);
    float4 rho = make_float4(tanhf(rr.x), tanhf(rr.y), tanhf(rr.z), tanhf(rr.w));
    float4 d = *(float4*)&sd[l][kq * 4];

    const float4* e = (const float4*)(eps + ((size_t)(b * Ln + l) * Tn) * Kn + kq * 4);
    float4* up = (float4*)(g_u + (size_t)(b * Ln + l) * Kn + kq * 4);
    const size_t ustep = (size_t)Bn * Ln * Kn / 4;

    float4 u = __ldcs(&e[0]);
    up[0] = u;
#pragma unroll
    for (int t = 1; t < Tn; t++) {
        float4 ev = __ldcs(&e[t * 2]);
        u.x = fmaf(rho.x, u.x, d.x * ev.x);
        u.y = fmaf(rho.y, u.y, d.y * ev.y);
        u.z = fmaf(rho.z, u.z, d.z * ev.z);
        u.w = fmaf(rho.w, u.w, d.w * ev.w);
        up[(size_t)t * ustep] = u;
    }
}

// ---------------------------------------------------------------------------
// Kernel 2 (persistent, software-pipelined):
//   out[n,:] = X[n,:] @ beta + u[s,b,l,:]
// Warp = 2 row-slots x 16 chunk-lanes. Lane (h,t) loads X float4 chunk t of
// rows {g*4+2h, g*4+2h+1}. beta rows 4t..4t+3 in 32 regs, loaded once/warp.
// Pipeline: X and u one iteration ahead, ids two iterations ahead.
// ---------------------------------------------------------------------------
#define FMA2(d_, a_, b_, c_) \
    asm("fma.rn.f32x2 %0, %1, %2, %3;" : "=l"(d_) : "l"(a_), "l"(b_), "l"(c_))
#define ADD2(d_, a_, b_) \
    asm("add.rn.f32x2 %0, %1, %2;" : "=l"(d_) : "l"(a_), "l"(b_))

__device__ __forceinline__ ull dupf(float x) {
    unsigned int w = __float_as_uint(x);
    ull q;
    asm("mov.b64 %0, {%1,%2};" : "=l"(q) : "r"(w), "r"(w));
    return q;
}

// Halving butterfly over 16-lane group: 4 pair-accumulators -> one complete
// pair per lane; lane t ends with pair p = ((t>>3)&1)*2 + ((t>>2)&1).
__device__ __forceinline__ ull reduce16(ull a0, ull a1, ull a2, ull a3, int t) {
    bool hi8 = (t & 8) != 0;
    ull s0 = hi8 ? a0 : a2;
    ull s1 = hi8 ? a1 : a3;
    ull k0 = hi8 ? a2 : a0;
    ull k1 = hi8 ? a3 : a1;
    ull r0 = __shfl_xor_sync(0xffffffffu, s0, 8);
    ull r1 = __shfl_xor_sync(0xffffffffu, s1, 8);
    ADD2(k0, k0, r0);
    ADD2(k1, k1, r1);
    bool hi4 = (t & 4) != 0;
    ull s = hi4 ? k0 : k1;
    ull k = hi4 ? k1 : k0;
    ull rv = __shfl_xor_sync(0xffffffffu, s, 4);
    ADD2(k, k, rv);
    ull rw = __shfl_xor_sync(0xffffffffu, k, 2);
    ADD2(k, k, rw);
    ull rx = __shfl_xor_sync(0xffffffffu, k, 1);
    ADD2(k, k, rx);
    return k;
}

__global__ void __launch_bounds__(256, 2)
main_kernel(const float* __restrict__ X,
            const int* __restrict__ batter_ids,
            const int* __restrict__ league_ids,
            const int* __restrict__ season_ids,
            const float* __restrict__ beta,
            float* __restrict__ out, int N) {
    int lane = threadIdx.x & 31;
    int h    = lane >> 4;            // row slot 0/1
    int t    = lane & 15;            // chunk 0..15
    bool writer = (t & 3) == 0;
    int p = t >> 2;                  // output pair for writer lanes

    // beta rows 4t..4t+3, 4 pairs each -> 16 u64 = 32 regs.
    ull B[4][4];
    const ulonglong2* bp = (const ulonglong2*)beta;
#pragma unroll
    for (int i = 0; i < 4; i++) {
        ulonglong2 lo = __ldg(&bp[(4 * t + i) * 2]);
        ulonglong2 hi = __ldg(&bp[(4 * t + i) * 2 + 1]);
        B[i][0] = lo.x; B[i][1] = lo.y; B[i][2] = hi.x; B[i][3] = hi.y;
    }

    int W  = gridDim.x * (blockDim.x >> 5);                   // total warps
    int gw = blockIdx.x * (blockDim.x >> 5) + (threadIdx.x >> 5);
    int G  = (N + 3) >> 2;                                    // 4-row groups

    // ---- prologue: X[g], ids[g]->u[g], ids[g+W] ----
    int g  = gw;
    int gc = min(g, G - 1);
    int n0 = gc * 4 + h * 2, n1 = n0 + 1;
    float4 xc0 = __ldcs((const float4*)(X + (size_t)n0 * NF) + t);
    float4 xc1 = __ldcs((const float4*)(X + (size_t)n1 * NF) + t);

    int As0 = 0, Ab0 = 0, Al0 = 0, As1 = 0, Ab1 = 0, Al1 = 0;
    float2 uc0 = make_float2(0.f, 0.f), uc1 = uc0;
    if (writer) {
        int s0 = season_ids[n0], b0 = batter_ids[n0], l0 = league_ids[n0];
        int s1 = season_ids[n1], b1 = batter_ids[n1], l1 = league_ids[n1];
        int ga = min(g + W, G - 1);
        int m0 = ga * 4 + h * 2, m1 = m0 + 1;
        As0 = season_ids[m0]; Ab0 = batter_ids[m0]; Al0 = league_ids[m0];
        As1 = season_ids[m1]; Ab1 = batter_ids[m1]; Al1 = league_ids[m1];
        uc0 = *(const float2*)(g_u + ((size_t)(s0 * Bn + b0) * Ln + l0) * Kn + p * 2);
        uc1 = *(const float2*)(g_u + ((size_t)(s1 * Bn + b1) * Ln + l1) * Kn + p * 2);
    }

    while (g < G) {
        int gn = g + W;
        int c1 = min(gn, G - 1);
        int c2 = min(gn + W, G - 1);

        // prefetch X[gn]
        int q0 = c1 * 4 + h * 2, q1 = q0 + 1;
        float4 xn0 = __ldcs((const float4*)(X + (size_t)q0 * NF) + t);
        float4 xn1 = __ldcs((const float4*)(X + (size_t)q1 * NF) + t);

        // prefetch ids[gn+W]; issue u[gn] gather from idsA (loaded last iter)
        int Bs0 = 0, Bb0 = 0, Bl0 = 0, Bs1 = 0, Bb1 = 0, Bl1 = 0;
        float2 un0 = make_float2(0.f, 0.f), un1 = un0;
        if (writer) {
            int m0 = c2 * 4 + h * 2, m1 = m0 + 1;
            Bs0 = season_ids[m0]; Bb0 = batter_ids[m0]; Bl0 = league_ids[m0];
            Bs1 = season_ids[m1]; Bb1 = batter_ids[m1]; Bl1 = league_ids[m1];
            un0 = *(const float2*)(g_u + ((size_t)(As0 * Bn + Ab0) * Ln + Al0) * Kn + p * 2);
            un1 = *(const float2*)(g_u + ((size_t)(As1 * Bn + Ab1) * Ln + Al1) * Kn + p * 2);
        }

        // compute on resident X
        ull a00 = 0, a01 = 0, a02 = 0, a03 = 0;
        ull a10 = 0, a11 = 0, a12 = 0, a13 = 0;
        float xs0[4] = {xc0.x, xc0.y, xc0.z, xc0.w};
        float xs1[4] = {xc1.x, xc1.y, xc1.z, xc1.w};
#pragma unroll
        for (int i = 0; i < 4; i++) {
            ull q0v = dupf(xs0[i]);
            ull q1v = dupf(xs1[i]);
            FMA2(a00, q0v, B[i][0], a00);
            FMA2(a01, q0v, B[i][1], a01);
            FMA2(a02, q0v, B[i][2], a02);
            FMA2(a03, q0v, B[i][3], a03);
            FMA2(a10, q1v, B[i][0], a10);
            FMA2(a11, q1v, B[i][1], a11);
            FMA2(a12, q1v, B[i][2], a12);
            FMA2(a13, q1v, B[i][3], a13);
        }

        ull K0 = reduce16(a00, a01, a02, a03, t);
        ull K1 = reduce16(a10, a11, a12, a13, t);

        if (writer) {
            int r0 = g * 4 + h * 2, r1 = r0 + 1;
            float f0, f1;
            if (r0 < N) {
                asm("mov.b64 {%0,%1}, %2;" : "=f"(f0), "=f"(f1) : "l"(K0));
                *(float2*)(out + (size_t)r0 * Kn + p * 2) =
                    make_float2(f0 + uc0.x, f1 + uc0.y);
            }
            if (r1 < N) {
                asm("mov.b64 {%0,%1}, %2;" : "=f"(f0), "=f"(f1) : "l"(K1));
                *(float2*)(out + (size_t)r1 * Kn + p * 2) =
                    make_float2(f0 + uc1.x, f1 + uc1.y);
            }
        }

        // shift pipeline
        xc0 = xn0; xc1 = xn1;
        uc0 = un0; uc1 = un1;
        As0 = Bs0; Ab0 = Bb0; Al0 = Bl0;
        As1 = Bs1; Ab1 = Bb1; Al1 = Bl1;
        g = gn;
    }
}

// ---------------------------------------------------------------------------
extern "C" void kernel_launch(void* const* d_in, const int* in_sizes, int n_in,
                              void* d_out, int out_size) {
    const float* X       = (const float*)d_in[0];
    const int*   bid     = (const int*)d_in[1];
    const int*   lid     = (const int*)d_in[2];
    const int*   sid     = (const int*)d_in[3];
    const float* beta    = (const float*)d_in[4];
    const float* raw_rho = (const float*)d_in[5];
    const float* Sigma   = (const float*)d_in[6];
    const float* eps     = (const float*)d_in[7];
    float*       out     = (float*)d_out;

    const int N = in_sizes[1];

    int chains4 = Bn * Ln * 2;
    scan_kernel<<<(chains4 + 255) / 256, 256>>>(eps, raw_rho, Sigma);

    main_kernel<<<304, 256>>>(X, bid, lid, sid, beta, out, N);
}